// round 3
// baseline (speedup 1.0000x reference)
#include <cuda_runtime.h>
#include <math.h>
#include <stdint.h>
#include <stddef.h>

// Problem constants
#define T_DIM 2048
#define D_DIM 2048
#define H_DIM 16
#define C_DIM 128

// Scratch (device globals: the sanctioned no-allocation workaround). 117 MB total.
__device__ __align__(128) float g_qkv[(size_t)T_DIM * 3 * D_DIM];          // 50 MB
__device__ __align__(128) float g_q[(size_t)H_DIM * T_DIM * C_DIM];        // 16.8 MB
__device__ __align__(128) float g_k[(size_t)H_DIM * T_DIM * C_DIM];
__device__ __align__(128) float g_v[(size_t)H_DIM * T_DIM * C_DIM];
__device__ __align__(128) float g_ao[(size_t)T_DIM * D_DIM];               // 16.8 MB

#define BM 128
#define BN 128
#define BK 16
#define TM 8
#define TN 8

// ---------------------------------------------------------------------------
// NT GEMM: C[m,n] = scale * sum_k A[m,k]*B[n,k] (+ bias[n])
// A row-major [M,K] (lda), B row-major [N,K] (ldb). Grid exactly covers M,N.
// ---------------------------------------------------------------------------
__global__ __launch_bounds__(256)
void gemm_nt_kernel(const float* __restrict__ A, int lda,
                    const float* __restrict__ B, int ldb,
                    float* __restrict__ C, int ldc,
                    const float* __restrict__ bias,
                    int K)
{
    const int m0 = blockIdx.y * BM;
    const int n0 = blockIdx.x * BN;

    __shared__ float As[BK][BM];
    __shared__ float Bs[BK][BN];

    const int tid  = threadIdx.x;
    const int tx   = tid & 15;
    const int ty   = tid >> 4;
    const int lrow = tid >> 2;         // 0..63
    const int lcol = (tid & 3) << 2;   // 0,4,8,12

    float acc[TM][TN];
#pragma unroll
    for (int i = 0; i < TM; i++)
#pragma unroll
        for (int j = 0; j < TN; j++) acc[i][j] = 0.f;

    for (int k0 = 0; k0 < K; k0 += BK) {
#pragma unroll
        for (int p = 0; p < 2; p++) {
            const int r = lrow + p * 64;
            float4 va = *(const float4*)(A + (size_t)(m0 + r) * lda + k0 + lcol);
            As[lcol + 0][r] = va.x;
            As[lcol + 1][r] = va.y;
            As[lcol + 2][r] = va.z;
            As[lcol + 3][r] = va.w;
            float4 vb = *(const float4*)(B + (size_t)(n0 + r) * ldb + k0 + lcol);
            Bs[lcol + 0][r] = vb.x;
            Bs[lcol + 1][r] = vb.y;
            Bs[lcol + 2][r] = vb.z;
            Bs[lcol + 3][r] = vb.w;
        }
        __syncthreads();
#pragma unroll
        for (int k = 0; k < BK; k++) {
            float4 a0 = *(const float4*)&As[k][ty * TM];
            float4 a1 = *(const float4*)&As[k][ty * TM + 4];
            float4 b0 = *(const float4*)&Bs[k][tx * TN];
            float4 b1 = *(const float4*)&Bs[k][tx * TN + 4];
            float ra[TM] = {a0.x, a0.y, a0.z, a0.w, a1.x, a1.y, a1.z, a1.w};
            float rb[TN] = {b0.x, b0.y, b0.z, b0.w, b1.x, b1.y, b1.z, b1.w};
#pragma unroll
            for (int i = 0; i < TM; i++)
#pragma unroll
                for (int j = 0; j < TN; j++)
                    acc[i][j] += ra[i] * rb[j];
        }
        __syncthreads();
    }

#pragma unroll
    for (int i = 0; i < TM; i++) {
        const int row = m0 + ty * TM + i;
#pragma unroll
        for (int j = 0; j < TN; j += 4) {
            const int col = n0 + tx * TN + j;
            float4 o;
            o.x = acc[i][j + 0];
            o.y = acc[i][j + 1];
            o.z = acc[i][j + 2];
            o.w = acc[i][j + 3];
            if (bias) {
                o.x += bias[col + 0];
                o.y += bias[col + 1];
                o.z += bias[col + 2];
                o.w += bias[col + 3];
            }
            *(float4*)(C + (size_t)row * ldc + col) = o;
        }
    }
}

// ---------------------------------------------------------------------------
// Per-(t,h) LayerNorm over C=128 + RoPE for q and k; pass-through for v.
// Output layout [H, T, C]. 128 threads = one c each.
// ---------------------------------------------------------------------------
__global__ __launch_bounds__(128)
void lnrope_kernel(const float* __restrict__ qkv,
                   const float* __restrict__ qw,
                   const float* __restrict__ kw,
                   float* __restrict__ Q, float* __restrict__ Ko,
                   float* __restrict__ V)
{
    const int t = blockIdx.x, h = blockIdx.y, c = threadIdx.x;
    const size_t base = (size_t)t * (3 * D_DIM) + (size_t)h * C_DIM + c;
    const float qv = qkv[base];
    const float kv = qkv[base + D_DIM];
    const float vv = qkv[base + 2 * D_DIM];

    __shared__ float red[4][4];
    float s0 = qv, s1 = qv * qv, s2 = kv, s3 = kv * kv;
#pragma unroll
    for (int o = 16; o; o >>= 1) {
        s0 += __shfl_xor_sync(0xffffffffu, s0, o);
        s1 += __shfl_xor_sync(0xffffffffu, s1, o);
        s2 += __shfl_xor_sync(0xffffffffu, s2, o);
        s3 += __shfl_xor_sync(0xffffffffu, s3, o);
    }
    const int w = c >> 5;
    if ((c & 31) == 0) { red[w][0] = s0; red[w][1] = s1; red[w][2] = s2; red[w][3] = s3; }
    __syncthreads();
    s0 = red[0][0] + red[1][0] + red[2][0] + red[3][0];
    s1 = red[0][1] + red[1][1] + red[2][1] + red[3][1];
    s2 = red[0][2] + red[1][2] + red[2][2] + red[3][2];
    s3 = red[0][3] + red[1][3] + red[2][3] + red[3][3];

    const float inv_n = 1.0f / (float)C_DIM;
    const float muq = s0 * inv_n;
    const float muk = s2 * inv_n;
    const float varq = s1 * inv_n - muq * muq;
    const float vark = s3 * inv_n - muk * muk;
    const float qn = (qv - muq) * rsqrtf(varq + 1e-6f) * qw[c];
    const float kn = (kv - muk) * rsqrtf(vark + 1e-6f) * kw[c];

    __shared__ float qs[C_DIM], ks[C_DIM];
    qs[c] = qn; ks[c] = kn;
    __syncthreads();

    const int i = c >> 1;
    const float inv_freq = powf(10000.f, -(float)(2 * i) / (float)C_DIM);
    const float ang = (float)t * inv_freq;
    float sn, cs;
    sincosf(ang, &sn, &cs);
    const float qrot = (c & 1) ? qs[c - 1] : -qs[c + 1];
    const float krot = (c & 1) ? ks[c - 1] : -ks[c + 1];

    const size_t o = ((size_t)h * T_DIM + t) * C_DIM + c;
    Q[o]  = qn * cs + qrot * sn;
    Ko[o] = kn * cs + krot * sn;
    V[o]  = vv;
}

// ---------------------------------------------------------------------------
// Fused causal flash attention (fp32, online softmax).
// Grid: (T/64, H). Block: 256 threads (tx 0..15 cols, ty 0..15 rows).
// Per block: 64 query rows. Streams 64-row K/V tiles up to the diagonal.
// Each thread: S sub-tile 4x4, O sub-tile 4 rows x 8 cols (C=128 split by tx).
// Output written directly as [T, D] at column h*C.
// ---------------------------------------------------------------------------
#define FQ 64
#define FKT 64
#define FLASH_SMEM ((3 * FQ * C_DIM + FQ * FKT) * (int)sizeof(float))  // 114688 B

__global__ __launch_bounds__(256)
void flash_kernel(const float* __restrict__ Qg, const float* __restrict__ Kg,
                  const float* __restrict__ Vg, float* __restrict__ Og)
{
    extern __shared__ float sm[];
    float* Qs = sm;                    // [FQ][128]
    float* Ks = Qs + FQ * C_DIM;       // [FKT][128]
    float* Vs = Ks + FKT * C_DIM;      // [FKT][128]
    float* Ps = Vs + FKT * C_DIM;      // [FQ][FKT]

    const int m0 = blockIdx.x * FQ;
    const int h  = blockIdx.y;
    const float scale = 0.08838834764831845f;  // 1/sqrt(128)

    const float* Qh = Qg + (size_t)h * T_DIM * C_DIM;
    const float* Kh = Kg + (size_t)h * T_DIM * C_DIM;
    const float* Vh = Vg + (size_t)h * T_DIM * C_DIM;

    const int tid = threadIdx.x;
    const int tx  = tid & 15;
    const int ty  = tid >> 4;

    // Load + pre-scale Q tile (8192 floats, 8 float4 per thread)
#pragma unroll
    for (int i = 0; i < 8; i++) {
        const int e = (tid + i * 256) * 4;
        float4 v = *(const float4*)(Qh + (size_t)m0 * C_DIM + e);
        v.x *= scale; v.y *= scale; v.z *= scale; v.w *= scale;
        *(float4*)(Qs + e) = v;
    }

    float Oacc[4][8];
#pragma unroll
    for (int r = 0; r < 4; r++)
#pragma unroll
        for (int c = 0; c < 8; c++) Oacc[r][c] = 0.f;
    float mrow[4] = {-1e30f, -1e30f, -1e30f, -1e30f};
    float lrow[4] = {0.f, 0.f, 0.f, 0.f};

    for (int kt = 0; kt <= m0; kt += FKT) {
        __syncthreads();  // prior-iter PV (reads Vs/Ps) done before overwrite
#pragma unroll
        for (int i = 0; i < 8; i++) {
            const int e = (tid + i * 256) * 4;
            *(float4*)(Ks + e) = *(const float4*)(Kh + (size_t)kt * C_DIM + e);
            *(float4*)(Vs + e) = *(const float4*)(Vh + (size_t)kt * C_DIM + e);
        }
        __syncthreads();

        // S = Q(4 rows) . K(4 rows), K-dim 128
        float s[4][4];
#pragma unroll
        for (int r = 0; r < 4; r++)
#pragma unroll
            for (int c = 0; c < 4; c++) s[r][c] = 0.f;

        for (int kk = 0; kk < C_DIM; kk += 4) {
            float4 qv[4], kv[4];
#pragma unroll
            for (int r = 0; r < 4; r++)
                qv[r] = *(const float4*)(Qs + (ty * 4 + r) * C_DIM + kk);
#pragma unroll
            for (int c = 0; c < 4; c++)
                kv[c] = *(const float4*)(Ks + (tx * 4 + c) * C_DIM + kk);
#pragma unroll
            for (int r = 0; r < 4; r++)
#pragma unroll
                for (int c = 0; c < 4; c++)
                    s[r][c] += qv[r].x * kv[c].x + qv[r].y * kv[c].y
                             + qv[r].z * kv[c].z + qv[r].w * kv[c].w;
        }

        // Causal mask (only the diagonal tile needs it)
        if (kt == m0) {
#pragma unroll
            for (int r = 0; r < 4; r++)
#pragma unroll
                for (int c = 0; c < 4; c++)
                    if (tx * 4 + c > ty * 4 + r) s[r][c] = -1e30f;
        }

        // Online softmax per row (row group = 16 consecutive lanes within a warp)
#pragma unroll
        for (int r = 0; r < 4; r++) {
            float rm = fmaxf(fmaxf(s[r][0], s[r][1]), fmaxf(s[r][2], s[r][3]));
#pragma unroll
            for (int o = 8; o; o >>= 1)
                rm = fmaxf(rm, __shfl_xor_sync(0xffffffffu, rm, o));
            const float nm = fmaxf(mrow[r], rm);
            const float al = __expf(mrow[r] - nm);
            float rs = 0.f;
#pragma unroll
            for (int c = 0; c < 4; c++) {
                const float p = __expf(s[r][c] - nm);
                Ps[(ty * 4 + r) * FKT + tx * 4 + c] = p;
                rs += p;
            }
#pragma unroll
            for (int o = 8; o; o >>= 1)
                rs += __shfl_xor_sync(0xffffffffu, rs, o);
            lrow[r] = lrow[r] * al + rs;
            mrow[r] = nm;
#pragma unroll
            for (int c = 0; c < 8; c++) Oacc[r][c] *= al;
        }
        __syncthreads();  // Ps fully written

        // O += P (4 rows x 64) . V (64 x 8 cols at tx*8)
        for (int j = 0; j < FKT; j++) {
            float4 v0 = *(const float4*)(Vs + j * C_DIM + tx * 8);
            float4 v1 = *(const float4*)(Vs + j * C_DIM + tx * 8 + 4);
            const float vv[8] = {v0.x, v0.y, v0.z, v0.w, v1.x, v1.y, v1.z, v1.w};
#pragma unroll
            for (int r = 0; r < 4; r++) {
                const float p = Ps[(ty * 4 + r) * FKT + j];
#pragma unroll
                for (int c = 0; c < 8; c++)
                    Oacc[r][c] += p * vv[c];
            }
        }
    }

    // Normalize + store to [T, D] at column h*C
#pragma unroll
    for (int r = 0; r < 4; r++) {
        const float inv = 1.f / lrow[r];
        const size_t row = (size_t)(m0 + ty * 4 + r);
        float4 o0, o1;
        o0.x = Oacc[r][0] * inv; o0.y = Oacc[r][1] * inv;
        o0.z = Oacc[r][2] * inv; o0.w = Oacc[r][3] * inv;
        o1.x = Oacc[r][4] * inv; o1.y = Oacc[r][5] * inv;
        o1.z = Oacc[r][6] * inv; o1.w = Oacc[r][7] * inv;
        *(float4*)(Og + row * D_DIM + h * C_DIM + tx * 8)     = o0;
        *(float4*)(Og + row * D_DIM + h * C_DIM + tx * 8 + 4) = o1;
    }
}

// ---------------------------------------------------------------------------
extern "C" void kernel_launch(void* const* d_in, const int* in_sizes, int n_in,
                              void* d_out, int out_size)
{
    const float* x      = (const float*)d_in[0];
    const float* W_attn = (const float*)d_in[1];
    const float* b_attn = (const float*)d_in[2];
    const float* W_proj = (const float*)d_in[3];
    const float* b_proj = (const float*)d_in[4];
    const float* q_ln_w = (const float*)d_in[5];
    const float* k_ln_w = (const float*)d_in[6];
    float* out = (float*)d_out;

    float *qkv, *q, *k, *v, *ao;
    cudaGetSymbolAddress((void**)&qkv, g_qkv);
    cudaGetSymbolAddress((void**)&q,   g_q);
    cudaGetSymbolAddress((void**)&k,   g_k);
    cudaGetSymbolAddress((void**)&v,   g_v);
    cudaGetSymbolAddress((void**)&ao,  g_ao);

    cudaFuncSetAttribute(flash_kernel,
                         cudaFuncAttributeMaxDynamicSharedMemorySize,
                         FLASH_SMEM);

    // 1) QKV = x @ W_attn^T + b_attn                [2048 x 6144]
    gemm_nt_kernel<<<dim3(3 * D_DIM / BN, T_DIM / BM), 256>>>(
        x, D_DIM, W_attn, D_DIM, qkv, 3 * D_DIM, b_attn, D_DIM);

    // 2) per-head LayerNorm + RoPE -> Q,K,V in [H,T,C]
    lnrope_kernel<<<dim3(T_DIM, H_DIM), 128>>>(qkv, q_ln_w, k_ln_w, q, k, v);

    // 3) fused causal attention -> ao [T, D]
    flash_kernel<<<dim3(T_DIM / FQ, H_DIM), 256, FLASH_SMEM>>>(q, k, v, ao);

    // 4) out = ao @ W_proj^T + b_proj
    gemm_nt_kernel<<<dim3(D_DIM / BN, T_DIM / BM), 256>>>(
        ao, D_DIM, W_proj, D_DIM, out, D_DIM, b_proj, D_DIM);
}

// round 5
// speedup vs baseline: 2.3414x; 2.3414x over previous
#include <cuda_runtime.h>
#include <cuda_bf16.h>
#include <math.h>
#include <stdint.h>
#include <stddef.h>

#define T_DIM 2048
#define D_DIM 2048
#define H_DIM 16
#define C_DIM 128

// ---------------- scratch (device globals; no runtime allocation) ----------
__device__ __align__(128) float g_qkv[(size_t)T_DIM * 3 * D_DIM];          // 50 MB
__device__ __align__(128) float g_q [(size_t)H_DIM * T_DIM * C_DIM];
__device__ __align__(128) float g_k [(size_t)H_DIM * T_DIM * C_DIM];
__device__ __align__(128) float g_v [(size_t)H_DIM * T_DIM * C_DIM];
__device__ __align__(128) float g_ao[(size_t)T_DIM * D_DIM];
__device__ __align__(128) __nv_bfloat16 g_xh [(size_t)T_DIM * D_DIM];
__device__ __align__(128) __nv_bfloat16 g_xl [(size_t)T_DIM * D_DIM];
__device__ __align__(128) __nv_bfloat16 g_wah[(size_t)3 * D_DIM * D_DIM];
__device__ __align__(128) __nv_bfloat16 g_wal[(size_t)3 * D_DIM * D_DIM];
__device__ __align__(128) __nv_bfloat16 g_wph[(size_t)D_DIM * D_DIM];
__device__ __align__(128) __nv_bfloat16 g_wpl[(size_t)D_DIM * D_DIM];
__device__ __align__(128) __nv_bfloat16 g_aoh[(size_t)T_DIM * D_DIM];
__device__ __align__(128) __nv_bfloat16 g_aol[(size_t)T_DIM * D_DIM];

// ---------------- small asm helpers ----------------------------------------
__device__ __forceinline__ uint32_t smem_u32(const void* p) {
    return (uint32_t)__cvta_generic_to_shared(p);
}
__device__ __forceinline__ void cpa16(void* s, const void* g) {
    asm volatile("cp.async.cg.shared.global [%0], [%1], 16;\n"
                 :: "r"(smem_u32(s)), "l"(g));
}
__device__ __forceinline__ void cpa_commit() {
    asm volatile("cp.async.commit_group;\n");
}
__device__ __forceinline__ void ldm_x4(uint32_t& d0, uint32_t& d1,
                                       uint32_t& d2, uint32_t& d3,
                                       const void* p) {
    asm volatile("ldmatrix.sync.aligned.m8n8.x4.shared.b16 {%0,%1,%2,%3}, [%4];\n"
                 : "=r"(d0), "=r"(d1), "=r"(d2), "=r"(d3)
                 : "r"(smem_u32(p)));
}
__device__ __forceinline__ void mma16816(float* c, const uint32_t* a,
                                         const uint32_t* b) {
    asm volatile("mma.sync.aligned.m16n8k16.row.col.f32.bf16.bf16.f32 "
                 "{%0,%1,%2,%3}, {%4,%5,%6,%7}, {%8,%9}, {%0,%1,%2,%3};\n"
                 : "+f"(c[0]), "+f"(c[1]), "+f"(c[2]), "+f"(c[3])
                 : "r"(a[0]), "r"(a[1]), "r"(a[2]), "r"(a[3]),
                   "r"(b[0]), "r"(b[1]));
}

// ---------------- fp32 -> bf16 (hi, lo) conversion --------------------------
__global__ __launch_bounds__(256)
void cvt_kernel(const float4* __restrict__ src,
                __nv_bfloat162* __restrict__ hi,
                __nv_bfloat162* __restrict__ lo, int n4)
{
    int i = blockIdx.x * 256 + threadIdx.x;
    if (i >= n4) return;
    float4 v = src[i];
    __nv_bfloat16 h0 = __float2bfloat16_rn(v.x);
    __nv_bfloat16 h1 = __float2bfloat16_rn(v.y);
    __nv_bfloat16 h2 = __float2bfloat16_rn(v.z);
    __nv_bfloat16 h3 = __float2bfloat16_rn(v.w);
    __nv_bfloat16 l0 = __float2bfloat16_rn(v.x - __bfloat162float(h0));
    __nv_bfloat16 l1 = __float2bfloat16_rn(v.y - __bfloat162float(h1));
    __nv_bfloat16 l2 = __float2bfloat16_rn(v.z - __bfloat162float(h2));
    __nv_bfloat16 l3 = __float2bfloat16_rn(v.w - __bfloat162float(h3));
    __nv_bfloat162 a; a.x = h0; a.y = h1;
    __nv_bfloat162 b; b.x = h2; b.y = h3;
    __nv_bfloat162 c; c.x = l0; c.y = l1;
    __nv_bfloat162 d; d.x = l2; d.y = l3;
    hi[2 * i] = a; hi[2 * i + 1] = b;
    lo[2 * i] = c; lo[2 * i + 1] = d;
}

// ---------------- bf16x3 NT GEMM (tensor cores) -----------------------------
// C[m,n] = sum_k (Ah+Al)[m,k]*(Bh+Bl)[n,k] + bias[n]  (3 HMMA passes)
// Block 128x128, BK=32, 8 warps (2x4), warp tile 64x32. lda=ldb=K, ldc=N.
// smem: dynamic, 2 stages x 32KB (static limit is 48KB -> must be dynamic).
#define GSTG 32768   // Ah(8K) Al(8K) Bh(8K) Bl(8K) per stage
#define GEMM_SMEM (2 * GSTG)

__device__ __forceinline__ void gemm_pass(const char* sA, const char* sB,
                                          float acc[4][4][4],
                                          int wm, int wn, int lane)
{
#pragma unroll
    for (int ks = 0; ks < 2; ks++) {
        uint32_t af[4][4];
#pragma unroll
        for (int im = 0; im < 4; im++) {
            int r  = wm * 64 + im * 16 + ((lane >> 3) & 1) * 8 + (lane & 7);
            int ch = 2 * ks + (lane >> 4);
            ldm_x4(af[im][0], af[im][1], af[im][2], af[im][3],
                   sA + r * 64 + ((ch ^ ((r >> 1) & 3)) << 4));
        }
        uint32_t bf_[4][2];
#pragma unroll
        for (int ip = 0; ip < 2; ip++) {
            int r  = wn * 32 + ip * 16 + ((lane >> 3) & 1) * 8 + (lane & 7);
            int ch = 2 * ks + (lane >> 4);
            uint32_t r0, r1, r2, r3;
            ldm_x4(r0, r1, r2, r3,
                   sB + r * 64 + ((ch ^ ((r >> 1) & 3)) << 4));
            bf_[2 * ip][0] = r0; bf_[2 * ip + 1][0] = r1;
            bf_[2 * ip][1] = r2; bf_[2 * ip + 1][1] = r3;
        }
#pragma unroll
        for (int im = 0; im < 4; im++)
#pragma unroll
            for (int in = 0; in < 4; in++)
                mma16816(acc[im][in], af[im], bf_[in]);
    }
}

__global__ __launch_bounds__(256)
void mma_gemm_nt(const __nv_bfloat16* __restrict__ Ah,
                 const __nv_bfloat16* __restrict__ Al,
                 const __nv_bfloat16* __restrict__ Bh,
                 const __nv_bfloat16* __restrict__ Bl,
                 float* __restrict__ C,
                 const float* __restrict__ bias,
                 int N, int K)
{
    extern __shared__ __align__(16) char smem_dyn[];
    char* stage[2] = { smem_dyn, smem_dyn + GSTG };

    const int tid  = threadIdx.x;
    const int wid  = tid >> 5, lane = tid & 31;
    const int wm   = wid >> 2, wn = wid & 3;
    const int m0   = blockIdx.y * 128, n0 = blockIdx.x * 128;

    float acc[4][4][4];
#pragma unroll
    for (int a = 0; a < 4; a++)
#pragma unroll
        for (int b = 0; b < 4; b++)
#pragma unroll
            for (int c = 0; c < 4; c++) acc[a][b][c] = 0.f;

    const int niter = K / 32;

    // prologue: stage 0
    {
        char* s = stage[0];
#pragma unroll
        for (int h = 0; h < 2; h++) {
            int c = tid + h * 256;
            int row = c >> 2, j = c & 3;
            int off = row * 64 + ((j ^ ((row >> 1) & 3)) << 4);
            size_t ga = (size_t)(m0 + row) * K + j * 8;
            size_t gb = (size_t)(n0 + row) * K + j * 8;
            cpa16(s + off,         Ah + ga);
            cpa16(s + 8192 + off,  Al + ga);
            cpa16(s + 16384 + off, Bh + gb);
            cpa16(s + 24576 + off, Bl + gb);
        }
        cpa_commit();
    }

    for (int i = 0; i < niter; i++) {
        if (i + 1 < niter) {
            char* s = stage[(i + 1) & 1];
            int k0 = (i + 1) * 32;
#pragma unroll
            for (int h = 0; h < 2; h++) {
                int c = tid + h * 256;
                int row = c >> 2, j = c & 3;
                int off = row * 64 + ((j ^ ((row >> 1) & 3)) << 4);
                size_t ga = (size_t)(m0 + row) * K + k0 + j * 8;
                size_t gb = (size_t)(n0 + row) * K + k0 + j * 8;
                cpa16(s + off,         Ah + ga);
                cpa16(s + 8192 + off,  Al + ga);
                cpa16(s + 16384 + off, Bh + gb);
                cpa16(s + 24576 + off, Bl + gb);
            }
            cpa_commit();
            asm volatile("cp.async.wait_group 1;\n");
        } else {
            asm volatile("cp.async.wait_group 0;\n");
        }
        __syncthreads();
        const char* s = stage[i & 1];
        gemm_pass(s,        s + 16384, acc, wm, wn, lane);  // Ah*Bh
        gemm_pass(s + 8192, s + 16384, acc, wm, wn, lane);  // Al*Bh
        gemm_pass(s,        s + 24576, acc, wm, wn, lane);  // Ah*Bl
        __syncthreads();
    }

    // epilogue
#pragma unroll
    for (int im = 0; im < 4; im++) {
        int row = m0 + wm * 64 + im * 16 + (lane >> 2);
#pragma unroll
        for (int in = 0; in < 4; in++) {
            int col = n0 + wn * 32 + in * 8 + 2 * (lane & 3);
            float b0 = bias[col], b1 = bias[col + 1];
            float2 o0, o1;
            o0.x = acc[im][in][0] + b0; o0.y = acc[im][in][1] + b1;
            o1.x = acc[im][in][2] + b0; o1.y = acc[im][in][3] + b1;
            *(float2*)(C + (size_t)row * N + col)       = o0;
            *(float2*)(C + (size_t)(row + 8) * N + col) = o1;
        }
    }
}

// ---------------- LayerNorm + RoPE ------------------------------------------
__global__ __launch_bounds__(128)
void lnrope_kernel(const float* __restrict__ qkv,
                   const float* __restrict__ qw,
                   const float* __restrict__ kw,
                   float* __restrict__ Q, float* __restrict__ Ko,
                   float* __restrict__ V)
{
    const int t = blockIdx.x, h = blockIdx.y, c = threadIdx.x;
    const size_t base = (size_t)t * (3 * D_DIM) + (size_t)h * C_DIM + c;
    const float qv = qkv[base];
    const float kv = qkv[base + D_DIM];
    const float vv = qkv[base + 2 * D_DIM];

    __shared__ float red[4][4];
    float s0 = qv, s1 = qv * qv, s2 = kv, s3 = kv * kv;
#pragma unroll
    for (int o = 16; o; o >>= 1) {
        s0 += __shfl_xor_sync(0xffffffffu, s0, o);
        s1 += __shfl_xor_sync(0xffffffffu, s1, o);
        s2 += __shfl_xor_sync(0xffffffffu, s2, o);
        s3 += __shfl_xor_sync(0xffffffffu, s3, o);
    }
    const int w = c >> 5;
    if ((c & 31) == 0) { red[w][0] = s0; red[w][1] = s1; red[w][2] = s2; red[w][3] = s3; }
    __syncthreads();
    s0 = red[0][0] + red[1][0] + red[2][0] + red[3][0];
    s1 = red[0][1] + red[1][1] + red[2][1] + red[3][1];
    s2 = red[0][2] + red[1][2] + red[2][2] + red[3][2];
    s3 = red[0][3] + red[1][3] + red[2][3] + red[3][3];

    const float inv_n = 1.0f / (float)C_DIM;
    const float muq = s0 * inv_n, muk = s2 * inv_n;
    const float varq = s1 * inv_n - muq * muq;
    const float vark = s3 * inv_n - muk * muk;
    const float qn = (qv - muq) * rsqrtf(varq + 1e-6f) * qw[c];
    const float kn = (kv - muk) * rsqrtf(vark + 1e-6f) * kw[c];

    __shared__ float qs[C_DIM], ks[C_DIM];
    qs[c] = qn; ks[c] = kn;
    __syncthreads();

    const int i = c >> 1;
    const float inv_freq = powf(10000.f, -(float)(2 * i) / (float)C_DIM);
    float sn, cs;
    sincosf((float)t * inv_freq, &sn, &cs);
    const float qrot = (c & 1) ? qs[c - 1] : -qs[c + 1];
    const float krot = (c & 1) ? ks[c - 1] : -ks[c + 1];

    const size_t o = ((size_t)h * T_DIM + t) * C_DIM + c;
    Q[o]  = qn * cs + qrot * sn;
    Ko[o] = kn * cs + krot * sn;
    V[o]  = vv;
}

// ---------------- fused causal flash attention v2 ---------------------------
// FQ=128 q-rows, FKT=128 kv-rows per tile, 256 threads, 8x8 register tiles.
// smem: Qs(64K, plain) + Ks(64K, chunk-swizzled; reused for P) + Vs(64K, plain).
#define FLASH2_SMEM (3 * 128 * 128 * 4)

__global__ __launch_bounds__(256)
void flash2_kernel(const float* __restrict__ Qg, const float* __restrict__ Kg,
                   const float* __restrict__ Vg, float* __restrict__ Og)
{
    extern __shared__ float sm[];
    float* Qs = sm;                 // [128][128]
    float* Ks = sm + 16384;         // [128][128] swizzled; doubles as P
    float* Vs = sm + 32768;         // [128][128]

    const int m0 = blockIdx.x * 128;
    const int h  = blockIdx.y;
    const float scale = 0.08838834764831845f;  // 1/sqrt(128)

    const float4* Q4 = (const float4*)(Qg + (size_t)h * T_DIM * C_DIM);
    const float4* K4 = (const float4*)(Kg + (size_t)h * T_DIM * C_DIM);
    const float4* V4 = (const float4*)(Vg + (size_t)h * T_DIM * C_DIM);

    const int tid = threadIdx.x;
    const int tx  = tid & 15;        // 8 cols each
    const int ty  = tid >> 4;        // 8 rows each
    const int ty7 = ty & 7;

    // load + pre-scale Q (plain layout)
#pragma unroll
    for (int i = 0; i < 16; i++) {
        int idx = tid + i * 256;
        float4 v = Q4[m0 * 32 + idx];
        v.x *= scale; v.y *= scale; v.z *= scale; v.w *= scale;
        ((float4*)Qs)[idx] = v;
    }

    float Oa[8][8];
#pragma unroll
    for (int r = 0; r < 8; r++)
#pragma unroll
        for (int c = 0; c < 8; c++) Oa[r][c] = 0.f;
    float mr[8], lr[8];
#pragma unroll
    for (int r = 0; r < 8; r++) { mr[r] = -1e30f; lr[r] = 0.f; }

    for (int kt = 0; kt <= m0; kt += 128) {
        __syncthreads();   // prior PV reads of Ks/Vs complete
#pragma unroll
        for (int i = 0; i < 16; i++) {
            int idx = tid + i * 256;
            int row = idx >> 5, j32 = idx & 31;
            ((float4*)Ks)[row * 32 + (j32 ^ ((row >> 3) & 7))] = K4[kt * 32 + idx];
            ((float4*)Vs)[idx] = V4[kt * 32 + idx];
        }
        __syncthreads();

        // S = Q . K^T   (8x8 per thread)
        float s[8][8];
#pragma unroll
        for (int r = 0; r < 8; r++)
#pragma unroll
            for (int c = 0; c < 8; c++) s[r][c] = 0.f;

        for (int kk = 0; kk < 128; kk += 4) {
            float4 qv[8];
#pragma unroll
            for (int r = 0; r < 8; r++)
                qv[r] = *(const float4*)(Qs + (ty * 8 + r) * 128 + kk);
            const int ch = (((kk >> 2) ^ (tx & 7)) << 2);
#pragma unroll
            for (int c = 0; c < 8; c++) {
                float4 kv = *(const float4*)(Ks + (tx * 8 + c) * 128 + ch);
#pragma unroll
                for (int r = 0; r < 8; r++)
                    s[r][c] += qv[r].x * kv.x + qv[r].y * kv.y
                             + qv[r].z * kv.z + qv[r].w * kv.w;
            }
        }

        if (kt == m0) {
#pragma unroll
            for (int r = 0; r < 8; r++)
#pragma unroll
                for (int c = 0; c < 8; c++)
                    if (tx * 8 + c > ty * 8 + r) s[r][c] = -1e30f;
        }

        // online softmax (row group = 16 lanes sharing ty)
#pragma unroll
        for (int r = 0; r < 8; r++) {
            float rm = s[r][0];
#pragma unroll
            for (int c = 1; c < 8; c++) rm = fmaxf(rm, s[r][c]);
#pragma unroll
            for (int o = 8; o; o >>= 1)
                rm = fmaxf(rm, __shfl_xor_sync(0xffffffffu, rm, o));
            const float nm = fmaxf(mr[r], rm);
            const float al = __expf(mr[r] - nm);
            float rs = 0.f;
#pragma unroll
            for (int c = 0; c < 8; c++) {
                const float p = __expf(s[r][c] - nm);
                s[r][c] = p;
                rs += p;
            }
#pragma unroll
            for (int o = 8; o; o >>= 1)
                rs += __shfl_xor_sync(0xffffffffu, rs, o);
            lr[r] = lr[r] * al + rs;
            mr[r] = nm;
#pragma unroll
            for (int c = 0; c < 8; c++) Oa[r][c] *= al;
        }
        __syncthreads();   // all S reads of Ks done

        // write P over Ks (same swizzle as K layout)
#pragma unroll
        for (int r = 0; r < 8; r++) {
            const int qrow = ty * 8 + r;
            float4 p0, p1;
            p0.x = s[r][0]; p0.y = s[r][1]; p0.z = s[r][2]; p0.w = s[r][3];
            p1.x = s[r][4]; p1.y = s[r][5]; p1.z = s[r][6]; p1.w = s[r][7];
            *(float4*)(Ks + qrow * 128 + (((2 * tx) ^ ty7) << 2))     = p0;
            *(float4*)(Ks + qrow * 128 + (((2 * tx + 1) ^ ty7) << 2)) = p1;
        }
        __syncthreads();

        // O += P . V
        for (int j = 0; j < 128; j++) {
            float4 v0 = *(const float4*)(Vs + j * 128 + tx * 8);
            float4 v1 = *(const float4*)(Vs + j * 128 + tx * 8 + 4);
            const int swoff = ((((j >> 2) ^ ty7) << 2)) + (j & 3);
#pragma unroll
            for (int r = 0; r < 8; r++) {
                const float p = Ks[(ty * 8 + r) * 128 + swoff];
                Oa[r][0] += p * v0.x; Oa[r][1] += p * v0.y;
                Oa[r][2] += p * v0.z; Oa[r][3] += p * v0.w;
                Oa[r][4] += p * v1.x; Oa[r][5] += p * v1.y;
                Oa[r][6] += p * v1.z; Oa[r][7] += p * v1.w;
            }
        }
    }

    // normalize + store [T, D] at column h*C
#pragma unroll
    for (int r = 0; r < 8; r++) {
        const float inv = 1.f / lr[r];
        const size_t row = (size_t)(m0 + ty * 8 + r);
        float4 o0, o1;
        o0.x = Oa[r][0] * inv; o0.y = Oa[r][1] * inv;
        o0.z = Oa[r][2] * inv; o0.w = Oa[r][3] * inv;
        o1.x = Oa[r][4] * inv; o1.y = Oa[r][5] * inv;
        o1.z = Oa[r][6] * inv; o1.w = Oa[r][7] * inv;
        *(float4*)(Og + row * D_DIM + h * C_DIM + tx * 8)     = o0;
        *(float4*)(Og + row * D_DIM + h * C_DIM + tx * 8 + 4) = o1;
    }
}

// ---------------------------------------------------------------------------
extern "C" void kernel_launch(void* const* d_in, const int* in_sizes, int n_in,
                              void* d_out, int out_size)
{
    const float* x      = (const float*)d_in[0];
    const float* W_attn = (const float*)d_in[1];
    const float* b_attn = (const float*)d_in[2];
    const float* W_proj = (const float*)d_in[3];
    const float* b_proj = (const float*)d_in[4];
    const float* q_ln_w = (const float*)d_in[5];
    const float* k_ln_w = (const float*)d_in[6];
    float* out = (float*)d_out;

    float *qkv, *q, *k, *v, *ao;
    __nv_bfloat16 *xh, *xl, *wah, *wal, *wph, *wpl, *aoh, *aol;
    cudaGetSymbolAddress((void**)&qkv, g_qkv);
    cudaGetSymbolAddress((void**)&q,   g_q);
    cudaGetSymbolAddress((void**)&k,   g_k);
    cudaGetSymbolAddress((void**)&v,   g_v);
    cudaGetSymbolAddress((void**)&ao,  g_ao);
    cudaGetSymbolAddress((void**)&xh,  g_xh);
    cudaGetSymbolAddress((void**)&xl,  g_xl);
    cudaGetSymbolAddress((void**)&wah, g_wah);
    cudaGetSymbolAddress((void**)&wal, g_wal);
    cudaGetSymbolAddress((void**)&wph, g_wph);
    cudaGetSymbolAddress((void**)&wpl, g_wpl);
    cudaGetSymbolAddress((void**)&aoh, g_aoh);
    cudaGetSymbolAddress((void**)&aol, g_aol);

    cudaFuncSetAttribute(mma_gemm_nt,
                         cudaFuncAttributeMaxDynamicSharedMemorySize,
                         GEMM_SMEM);
    cudaFuncSetAttribute(flash2_kernel,
                         cudaFuncAttributeMaxDynamicSharedMemorySize,
                         FLASH2_SMEM);

    const int n4_x  = T_DIM * D_DIM / 4;
    const int n4_wa = 3 * D_DIM * D_DIM / 4;
    const int n4_wp = D_DIM * D_DIM / 4;

    // 0) split fp32 -> bf16 hi/lo
    cvt_kernel<<<n4_x  / 256, 256>>>((const float4*)x,      (__nv_bfloat162*)xh,  (__nv_bfloat162*)xl,  n4_x);
    cvt_kernel<<<n4_wa / 256, 256>>>((const float4*)W_attn, (__nv_bfloat162*)wah, (__nv_bfloat162*)wal, n4_wa);
    cvt_kernel<<<n4_wp / 256, 256>>>((const float4*)W_proj, (__nv_bfloat162*)wph, (__nv_bfloat162*)wpl, n4_wp);

    // 1) QKV = x @ W_attn^T + b_attn   (tensor cores, bf16x3)
    mma_gemm_nt<<<dim3(3 * D_DIM / 128, T_DIM / 128), 256, GEMM_SMEM>>>(
        xh, xl, wah, wal, qkv, b_attn, 3 * D_DIM, D_DIM);

    // 2) per-head LayerNorm + RoPE
    lnrope_kernel<<<dim3(T_DIM, H_DIM), 128>>>(qkv, q_ln_w, k_ln_w, q, k, v);

    // 3) fused causal attention -> ao [T, D]
    flash2_kernel<<<dim3(T_DIM / 128, H_DIM), 256, FLASH2_SMEM>>>(q, k, v, ao);

    // 4) split ao, then out = ao @ W_proj^T + b_proj
    cvt_kernel<<<n4_x / 256, 256>>>((const float4*)ao, (__nv_bfloat162*)aoh, (__nv_bfloat162*)aol, n4_x);
    mma_gemm_nt<<<dim3(D_DIM / 128, T_DIM / 128), 256, GEMM_SMEM>>>(
        aoh, aol, wph, wpl, out, b_proj, D_DIM, D_DIM);
}